// round 2
// baseline (speedup 1.0000x reference)
#include <cuda_runtime.h>
#include <cuda_fp16.h>
#include <math.h>

#define NNODES 50000
#define NEDGES 400000
#define FDIM   128
#define F3     384
#define NB     20
#define EPB    64      // edges per block in edge_kernel

__device__ float  g_h [(size_t)NNODES * FDIM];   // silu(ns@W1+b1)
__device__ __half g_so[(size_t)NNODES * F3];     // scalar_out (fp16)
__device__ __half g_nvh[(size_t)NNODES * F3];    // node_vector (fp16)

// ---------------------------------------------------------------------------
// out = concat(node_scalar, node_vector)  (residuals accumulated by atomics)
// ---------------------------------------------------------------------------
__global__ void copy_init_kernel(const float4* __restrict__ ns,
                                 const float4* __restrict__ nv,
                                 float4* __restrict__ out) {
    const int NS4 = NNODES * FDIM / 4;
    const int NT4 = NS4 + NNODES * F3 / 4;
    int i = blockIdx.x * blockDim.x + threadIdx.x;
    if (i < NT4) out[i] = (i < NS4) ? ns[i] : nv[i - NS4];
}

// ---------------------------------------------------------------------------
// fp32 -> fp16 conversion (vectorized)
// ---------------------------------------------------------------------------
__global__ void f2h_kernel(const float4* __restrict__ in,
                           uint2* __restrict__ out, int n4) {
    int i = blockIdx.x * blockDim.x + threadIdx.x;
    if (i < n4) {
        float4 v = in[i];
        __half2 h0 = __floats2half2_rn(v.x, v.y);
        __half2 h1 = __floats2half2_rn(v.z, v.w);
        out[i] = make_uint2(*(unsigned*)&h0, *(unsigned*)&h1);
    }
}

__device__ __forceinline__ float4 ld_half4(const __half* p) {
    uint2 u = *(const uint2*)p;
    __half2 h0 = *reinterpret_cast<__half2*>(&u.x);
    __half2 h1 = *reinterpret_cast<__half2*>(&u.y);
    float2 f0 = __half22float2(h0), f1 = __half22float2(h1);
    return make_float4(f0.x, f0.y, f1.x, f1.y);
}

// ---------------------------------------------------------------------------
// C[M,N] = act(A[M,K] @ W[K,N] + bias)   (register-tiled fp32 GEMM)
// BM=64, BN=64, BK=16, 256 threads, 4x4 per-thread tile
// HALF_OUT: emit __half instead of float
// ---------------------------------------------------------------------------
template<bool SILU, bool HALF_OUT>
__global__ __launch_bounds__(256)
void gemm_kernel(const float* __restrict__ A, const float* __restrict__ W,
                 const float* __restrict__ bias, void* __restrict__ Cv,
                 int M, int N, int K)
{
    const int BM = 64, BN = 64, BK = 16;
    __shared__ float As[BK][BM];
    __shared__ float Bs[BK][BN];

    int t  = threadIdx.x;
    int m0 = blockIdx.x * BM;
    int n0 = blockIdx.y * BN;
    int ty = t >> 4, tx = t & 15;

    int ar = t >> 2;            // 0..63
    int ak = (t & 3) << 2;      // 0,4,8,12
    int bk = t >> 4;            // 0..15
    int bn = (t & 15) << 2;     // 0..60

    float acc[4][4];
#pragma unroll
    for (int i = 0; i < 4; i++)
#pragma unroll
        for (int j = 0; j < 4; j++) acc[i][j] = 0.0f;

    for (int k0 = 0; k0 < K; k0 += BK) {
        float4 av = make_float4(0.f, 0.f, 0.f, 0.f);
        if (m0 + ar < M)
            av = *(const float4*)(A + (size_t)(m0 + ar) * K + k0 + ak);
        As[ak + 0][ar] = av.x;
        As[ak + 1][ar] = av.y;
        As[ak + 2][ar] = av.z;
        As[ak + 3][ar] = av.w;
        *(float4*)&Bs[bk][bn] = *(const float4*)(W + (size_t)(k0 + bk) * N + n0 + bn);
        __syncthreads();
#pragma unroll
        for (int k = 0; k < BK; k++) {
            float4 a4 = *(float4*)&As[k][ty << 2];
            float4 b4 = *(float4*)&Bs[k][tx << 2];
            float a[4] = {a4.x, a4.y, a4.z, a4.w};
            float b[4] = {b4.x, b4.y, b4.z, b4.w};
#pragma unroll
            for (int i = 0; i < 4; i++)
#pragma unroll
                for (int j = 0; j < 4; j++) acc[i][j] += a[i] * b[j];
        }
        __syncthreads();
    }

    float4 bb = *(const float4*)(bias + n0 + (tx << 2));
    float bv[4] = {bb.x, bb.y, bb.z, bb.w};
#pragma unroll
    for (int i = 0; i < 4; i++) {
        int m = m0 + (ty << 2) + i;
        if (m < M) {
            float v[4];
#pragma unroll
            for (int j = 0; j < 4; j++) {
                float x = acc[i][j] + bv[j];
                if (SILU) x = x / (1.0f + expf(-x));
                v[j] = x;
            }
            if (HALF_OUT) {
                __half2 h0 = __floats2half2_rn(v[0], v[1]);
                __half2 h1 = __floats2half2_rn(v[2], v[3]);
                uint2 o = make_uint2(*(unsigned*)&h0, *(unsigned*)&h1);
                *(uint2*)((__half*)Cv + (size_t)m * N + n0 + (tx << 2)) = o;
            } else {
                float4 o = make_float4(v[0], v[1], v[2], v[3]);
                *(float4*)((float*)Cv + (size_t)m * N + n0 + (tx << 2)) = o;
            }
        }
    }
}

// ---------------------------------------------------------------------------
// vector reduction (no return) : out[0..3] += v
// ---------------------------------------------------------------------------
__device__ __forceinline__ void red_add4(float* p, float4 v) {
    asm volatile("red.global.add.v4.f32 [%0], {%1, %2, %3, %4};"
                 :: "l"(p), "f"(v.x), "f"(v.y), "f"(v.z), "f"(v.w)
                 : "memory");
}

// ---------------------------------------------------------------------------
// Edge kernel: 64 edges / block of 256 threads (2 passes of 32).
//  fw = basis @ W_filter fused in registers; gathers read fp16 so/nvec
//  (working set 76.8 MB -> L2 resident); scatter via red.v4.f32.
// ---------------------------------------------------------------------------
__global__ __launch_bounds__(256)
void edge_kernel(const int2*   __restrict__ eidx,
                 const float*  __restrict__ edist,
                 const float*  __restrict__ ediff,
                 const float*  __restrict__ Wf,      // [NB][384] fp32
                 const float*  __restrict__ bf,      // [384]
                 const __half* __restrict__ nvec,    // [N,3,128] fp16
                 const __half* __restrict__ so,      // [N,384] fp16
                 float* __restrict__ out_s,          // [N,128]
                 float* __restrict__ out_v)          // [N,3,128]
{
    __shared__ float s_Wf[NB * F3];          // 30720 B
    __shared__ float s_basis[EPB * NB];      // 5120 B
    __shared__ float s_d[EPB], s_cut[EPB];
    __shared__ int   s_src[EPB], s_dst[EPB];
    __shared__ float s_unit[3][EPB];

    const float PI_C = 0.628318530717958648f;   // pi / 5

    int t  = threadIdx.x;
    int e0 = blockIdx.x * EPB;

    for (int i = t; i < NB * F3 / 4; i += 256)
        ((float4*)s_Wf)[i] = ((const float4*)Wf)[i];

    if (t < EPB) {
        int e = e0 + t;
        int2 ei = eidx[e];
        s_dst[t] = ei.x;
        s_src[t] = ei.y;
        float d = edist[e];
        s_d[t] = d;
        s_cut[t] = (d < 5.0f) ? 0.5f * (cosf(d * PI_C) + 1.0f) : 0.0f;
        float inv = 1.0f / d;
        s_unit[0][t] = ediff[e * 3 + 0] * inv;
        s_unit[1][t] = ediff[e * 3 + 1] * inv;
        s_unit[2][t] = ediff[e * 3 + 2] * inv;
    }
    __syncthreads();

    // sine basis with explicit range reduction
    for (int i = t; i < EPB * NB; i += 256) {
        int e = i / NB, n = i % NB;
        float d = s_d[e];
        float x = d * (float)(n + 1) * PI_C;
        x -= 6.2831853071795865f * rintf(x * 0.15915494309189534f);
        s_basis[i] = sinf(x) / d;
    }
    __syncthreads();

    int cg = t & 31;          // column group (lane)
    int eg = t >> 5;          // warp id 0..7
    int cb = cg << 2;         // base channel 0..124

    float4 bf0 = *(const float4*)&bf[cb];
    float4 bf1 = *(const float4*)&bf[FDIM + cb];
    float4 bf2 = *(const float4*)&bf[2 * FDIM + cb];

#pragma unroll
    for (int half = 0; half < EPB / 32; half++) {
        int egg = half * 8 + eg;              // edge group 0..15

        float acc[4][12];
#pragma unroll
        for (int i = 0; i < 4; i++)
#pragma unroll
            for (int j = 0; j < 12; j++) acc[i][j] = 0.0f;

        const float* bas = &s_basis[(egg << 2) * NB];
#pragma unroll
        for (int k = 0; k < NB; k++) {
            float be[4];
#pragma unroll
            for (int i = 0; i < 4; i++) be[i] = bas[i * NB + k];
            float4 w0 = *(float4*)&s_Wf[k * F3 + cb];
            float4 w1 = *(float4*)&s_Wf[k * F3 + FDIM + cb];
            float4 w2 = *(float4*)&s_Wf[k * F3 + 2 * FDIM + cb];
#pragma unroll
            for (int i = 0; i < 4; i++) {
                acc[i][0] += be[i] * w0.x; acc[i][1] += be[i] * w0.y;
                acc[i][2] += be[i] * w0.z; acc[i][3] += be[i] * w0.w;
                acc[i][4] += be[i] * w1.x; acc[i][5] += be[i] * w1.y;
                acc[i][6] += be[i] * w1.z; acc[i][7] += be[i] * w1.w;
                acc[i][8] += be[i] * w2.x; acc[i][9] += be[i] * w2.y;
                acc[i][10]+= be[i] * w2.z; acc[i][11]+= be[i] * w2.w;
            }
        }

#pragma unroll
        for (int i = 0; i < 4; i++) {
            int e   = (egg << 2) + i;
            int src = s_src[e];
            int dst = s_dst[e];
            float cw = s_cut[e];

            const __half* sor = so + (size_t)src * F3 + cb;
            float4 s0 = ld_half4(sor);
            float4 s1 = ld_half4(sor + FDIM);
            float4 s2 = ld_half4(sor + 2 * FDIM);

            float4 gs, ge, ms;
            gs.x = (acc[i][0] + bf0.x) * cw * s0.x;
            gs.y = (acc[i][1] + bf0.y) * cw * s0.y;
            gs.z = (acc[i][2] + bf0.z) * cw * s0.z;
            gs.w = (acc[i][3] + bf0.w) * cw * s0.w;
            ge.x = (acc[i][4] + bf1.x) * cw * s1.x;
            ge.y = (acc[i][5] + bf1.y) * cw * s1.y;
            ge.z = (acc[i][6] + bf1.z) * cw * s1.z;
            ge.w = (acc[i][7] + bf1.w) * cw * s1.w;
            ms.x = (acc[i][8] + bf2.x) * cw * s2.x;
            ms.y = (acc[i][9] + bf2.y) * cw * s2.y;
            ms.z = (acc[i][10]+ bf2.z) * cw * s2.z;
            ms.w = (acc[i][11]+ bf2.w) * cw * s2.w;

            red_add4(out_s + (size_t)dst * FDIM + cb, ms);

            const __half* nvp = nvec + (size_t)src * F3 + cb;
            float u0 = s_unit[0][e], u1 = s_unit[1][e], u2 = s_unit[2][e];

            float4 v, m;
            v = ld_half4(nvp);
            m.x = v.x * gs.x + ge.x * u0;  m.y = v.y * gs.y + ge.y * u0;
            m.z = v.z * gs.z + ge.z * u0;  m.w = v.w * gs.w + ge.w * u0;
            red_add4(out_v + (size_t)dst * F3 + cb, m);

            v = ld_half4(nvp + FDIM);
            m.x = v.x * gs.x + ge.x * u1;  m.y = v.y * gs.y + ge.y * u1;
            m.z = v.z * gs.z + ge.z * u1;  m.w = v.w * gs.w + ge.w * u1;
            red_add4(out_v + (size_t)dst * F3 + FDIM + cb, m);

            v = ld_half4(nvp + 2 * FDIM);
            m.x = v.x * gs.x + ge.x * u2;  m.y = v.y * gs.y + ge.y * u2;
            m.z = v.z * gs.z + ge.z * u2;  m.w = v.w * gs.w + ge.w * u2;
            red_add4(out_v + (size_t)dst * F3 + 2 * FDIM + cb, m);
        }
    }
}

// ---------------------------------------------------------------------------
extern "C" void kernel_launch(void* const* d_in, const int* in_sizes, int n_in,
                              void* d_out, int out_size) {
    const int2*  eidx  = (const int2*) d_in[0];
    const float* edist = (const float*)d_in[1];
    const float* ediff = (const float*)d_in[2];
    const float* ns    = (const float*)d_in[3];
    const float* nv    = (const float*)d_in[4];
    const float* Wf    = (const float*)d_in[5];
    const float* bf    = (const float*)d_in[6];
    const float* W1    = (const float*)d_in[7];
    const float* b1    = (const float*)d_in[8];
    const float* W2    = (const float*)d_in[9];
    const float* b2    = (const float*)d_in[10];
    float* out = (float*)d_out;

    float  *h_ptr;
    __half *so_ptr, *nvh_ptr;
    cudaGetSymbolAddress((void**)&h_ptr,   g_h);
    cudaGetSymbolAddress((void**)&so_ptr,  g_so);
    cudaGetSymbolAddress((void**)&nvh_ptr, g_nvh);

    // 1) out = concat(node_scalar, node_vector)
    int tot4 = (NNODES * FDIM + NNODES * F3) / 4;
    copy_init_kernel<<<(tot4 + 255) / 256, 256>>>(
        (const float4*)ns, (const float4*)nv, (float4*)out);

    // 2) node_vector -> fp16
    int nv4 = NNODES * F3 / 4;
    f2h_kernel<<<(nv4 + 255) / 256, 256>>>(
        (const float4*)nv, (uint2*)nvh_ptr, nv4);

    // 3) h = silu(ns @ W1 + b1)   (fp32)
    gemm_kernel<true, false><<<dim3((NNODES + 63) / 64, FDIM / 64), 256>>>(
        ns, W1, b1, h_ptr, NNODES, FDIM, FDIM);

    // 4) scalar_out = h @ W2 + b2  (fp16 out)
    gemm_kernel<false, true><<<dim3((NNODES + 63) / 64, F3 / 64), 256>>>(
        h_ptr, W2, b2, so_ptr, NNODES, F3, FDIM);

    // 5) edge messages + scatter-add residuals
    edge_kernel<<<NEDGES / EPB, 256>>>(
        eidx, edist, ediff, Wf, bf, nvh_ptr, so_ptr,
        out, out + (size_t)NNODES * FDIM);
}

// round 3
// speedup vs baseline: 7.1774x; 7.1774x over previous
#include <cuda_runtime.h>
#include <cuda_fp16.h>
#include <math.h>

#define NNODES 50000
#define NEDGES 400000
#define FDIM   128
#define F3     384
#define NB     20

__device__ float  g_h [(size_t)NNODES * FDIM];   // silu(ns@W1+b1)
__device__ __half g_so[(size_t)NNODES * F3];     // scalar_out (fp16)
__device__ __half g_nvh[(size_t)NNODES * F3];    // node_vector (fp16)

// ---------------------------------------------------------------------------
// out = concat(node_scalar, node_vector)
// ---------------------------------------------------------------------------
__global__ void copy_init_kernel(const float4* __restrict__ ns,
                                 const float4* __restrict__ nv,
                                 float4* __restrict__ out) {
    const int NS4 = NNODES * FDIM / 4;
    const int NT4 = NS4 + NNODES * F3 / 4;
    int i = blockIdx.x * blockDim.x + threadIdx.x;
    if (i < NT4) out[i] = (i < NS4) ? ns[i] : nv[i - NS4];
}

// ---------------------------------------------------------------------------
// fp32 -> fp16 conversion (vectorized)
// ---------------------------------------------------------------------------
__global__ void f2h_kernel(const float4* __restrict__ in,
                           uint2* __restrict__ out, int n4) {
    int i = blockIdx.x * blockDim.x + threadIdx.x;
    if (i < n4) {
        float4 v = in[i];
        __half2 h0 = __floats2half2_rn(v.x, v.y);
        __half2 h1 = __floats2half2_rn(v.z, v.w);
        out[i] = make_uint2(*(unsigned*)&h0, *(unsigned*)&h1);
    }
}

__device__ __forceinline__ float4 ld_half4(const __half* p) {
    uint2 u = *(const uint2*)p;
    __half2 h0 = *reinterpret_cast<__half2*>(&u.x);
    __half2 h1 = *reinterpret_cast<__half2*>(&u.y);
    float2 f0 = __half22float2(h0), f1 = __half22float2(h1);
    return make_float4(f0.x, f0.y, f1.x, f1.y);
}

// ---------------------------------------------------------------------------
// C[M,N] = act(A[M,K] @ W[K,N] + bias)   (register-tiled fp32 GEMM)
// ---------------------------------------------------------------------------
template<bool SILU, bool HALF_OUT>
__global__ __launch_bounds__(256)
void gemm_kernel(const float* __restrict__ A, const float* __restrict__ W,
                 const float* __restrict__ bias, void* __restrict__ Cv,
                 int M, int N, int K)
{
    const int BM = 64, BN = 64, BK = 16;
    __shared__ float As[BK][BM];
    __shared__ float Bs[BK][BN];

    int t  = threadIdx.x;
    int m0 = blockIdx.x * BM;
    int n0 = blockIdx.y * BN;
    int ty = t >> 4, tx = t & 15;

    int ar = t >> 2;
    int ak = (t & 3) << 2;
    int bk = t >> 4;
    int bn = (t & 15) << 2;

    float acc[4][4];
#pragma unroll
    for (int i = 0; i < 4; i++)
#pragma unroll
        for (int j = 0; j < 4; j++) acc[i][j] = 0.0f;

    for (int k0 = 0; k0 < K; k0 += BK) {
        float4 av = make_float4(0.f, 0.f, 0.f, 0.f);
        if (m0 + ar < M)
            av = *(const float4*)(A + (size_t)(m0 + ar) * K + k0 + ak);
        As[ak + 0][ar] = av.x;
        As[ak + 1][ar] = av.y;
        As[ak + 2][ar] = av.z;
        As[ak + 3][ar] = av.w;
        *(float4*)&Bs[bk][bn] = *(const float4*)(W + (size_t)(k0 + bk) * N + n0 + bn);
        __syncthreads();
#pragma unroll
        for (int k = 0; k < BK; k++) {
            float4 a4 = *(float4*)&As[k][ty << 2];
            float4 b4 = *(float4*)&Bs[k][tx << 2];
            float a[4] = {a4.x, a4.y, a4.z, a4.w};
            float b[4] = {b4.x, b4.y, b4.z, b4.w};
#pragma unroll
            for (int i = 0; i < 4; i++)
#pragma unroll
                for (int j = 0; j < 4; j++) acc[i][j] += a[i] * b[j];
        }
        __syncthreads();
    }

    float4 bb = *(const float4*)(bias + n0 + (tx << 2));
    float bv[4] = {bb.x, bb.y, bb.z, bb.w};
#pragma unroll
    for (int i = 0; i < 4; i++) {
        int m = m0 + (ty << 2) + i;
        if (m < M) {
            float v[4];
#pragma unroll
            for (int j = 0; j < 4; j++) {
                float x = acc[i][j] + bv[j];
                if (SILU) x = x / (1.0f + expf(-x));
                v[j] = x;
            }
            if (HALF_OUT) {
                __half2 h0 = __floats2half2_rn(v[0], v[1]);
                __half2 h1 = __floats2half2_rn(v[2], v[3]);
                uint2 o = make_uint2(*(unsigned*)&h0, *(unsigned*)&h1);
                *(uint2*)((__half*)Cv + (size_t)m * N + n0 + (tx << 2)) = o;
            } else {
                float4 o = make_float4(v[0], v[1], v[2], v[3]);
                *(float4*)((float*)Cv + (size_t)m * N + n0 + (tx << 2)) = o;
            }
        }
    }
}

// ---------------------------------------------------------------------------
__device__ __forceinline__ void red_add4(float* p, float4 v) {
    asm volatile("red.global.add.v4.f32 [%0], {%1, %2, %3, %4};"
                 :: "l"(p), "f"(v.x), "f"(v.y), "f"(v.z), "f"(v.w)
                 : "memory");
}

// ---------------------------------------------------------------------------
// Edge kernel: EXACT round-1 structure (32 edges / 256 threads, single pass),
// only change: so/nvec gathers read fp16.
// ---------------------------------------------------------------------------
__global__ __launch_bounds__(256)
void edge_kernel(const int2*   __restrict__ eidx,
                 const float*  __restrict__ edist,
                 const float*  __restrict__ ediff,
                 const float*  __restrict__ Wf,      // [NB][384] fp32
                 const float*  __restrict__ bf,      // [384]
                 const __half* __restrict__ nvec,    // [N,3,128] fp16
                 const __half* __restrict__ so,      // [N,384] fp16
                 float* __restrict__ out_s,          // [N,128]
                 float* __restrict__ out_v)          // [N,3,128]
{
    __shared__ float s_Wf[NB * F3];
    __shared__ float s_basis[32 * NB];
    __shared__ float s_d[32], s_cut[32];
    __shared__ int   s_src[32], s_dst[32];
    __shared__ float s_unit[3][32];

    const float PI_C = 0.628318530717958648f;   // pi / 5

    int t  = threadIdx.x;
    int e0 = blockIdx.x << 5;

    for (int i = t; i < NB * F3 / 4; i += 256)
        ((float4*)s_Wf)[i] = ((const float4*)Wf)[i];

    if (t < 32) {
        int e = e0 + t;
        int2 ei = eidx[e];
        s_dst[t] = ei.x;
        s_src[t] = ei.y;
        float d = edist[e];
        s_d[t] = d;
        s_cut[t] = (d < 5.0f) ? 0.5f * (cosf(d * PI_C) + 1.0f) : 0.0f;
        float inv = 1.0f / d;
        s_unit[0][t] = ediff[e * 3 + 0] * inv;
        s_unit[1][t] = ediff[e * 3 + 1] * inv;
        s_unit[2][t] = ediff[e * 3 + 2] * inv;
    }
    __syncthreads();

    for (int i = t; i < 32 * NB; i += 256) {
        int e = i / NB, n = i % NB;
        float d = s_d[e];
        float x = d * (float)(n + 1) * PI_C;
        x -= 6.2831853071795865f * rintf(x * 0.15915494309189534f);
        s_basis[i] = sinf(x) / d;
    }
    __syncthreads();

    int cg = t & 31;
    int eg = t >> 5;
    int cb = cg << 2;

    float acc[4][12];
#pragma unroll
    for (int i = 0; i < 4; i++)
#pragma unroll
        for (int j = 0; j < 12; j++) acc[i][j] = 0.0f;

    const float* bas = &s_basis[(eg << 2) * NB];
#pragma unroll
    for (int k = 0; k < NB; k++) {
        float be[4];
#pragma unroll
        for (int i = 0; i < 4; i++) be[i] = bas[i * NB + k];
        float4 w0 = *(float4*)&s_Wf[k * F3 + cb];
        float4 w1 = *(float4*)&s_Wf[k * F3 + FDIM + cb];
        float4 w2 = *(float4*)&s_Wf[k * F3 + 2 * FDIM + cb];
#pragma unroll
        for (int i = 0; i < 4; i++) {
            acc[i][0] += be[i] * w0.x; acc[i][1] += be[i] * w0.y;
            acc[i][2] += be[i] * w0.z; acc[i][3] += be[i] * w0.w;
            acc[i][4] += be[i] * w1.x; acc[i][5] += be[i] * w1.y;
            acc[i][6] += be[i] * w1.z; acc[i][7] += be[i] * w1.w;
            acc[i][8] += be[i] * w2.x; acc[i][9] += be[i] * w2.y;
            acc[i][10]+= be[i] * w2.z; acc[i][11]+= be[i] * w2.w;
        }
    }

    float4 bf0 = *(const float4*)&bf[cb];
    float4 bf1 = *(const float4*)&bf[FDIM + cb];
    float4 bf2 = *(const float4*)&bf[2 * FDIM + cb];

#pragma unroll
    for (int i = 0; i < 4; i++) {
        int e   = (eg << 2) + i;
        int src = s_src[e];
        int dst = s_dst[e];
        float cw = s_cut[e];

        const __half* sor = so + (size_t)src * F3 + cb;
        float4 s0 = ld_half4(sor);
        float4 s1 = ld_half4(sor + FDIM);
        float4 s2 = ld_half4(sor + 2 * FDIM);

        float4 gs, ge, ms;
        gs.x = (acc[i][0] + bf0.x) * cw * s0.x;
        gs.y = (acc[i][1] + bf0.y) * cw * s0.y;
        gs.z = (acc[i][2] + bf0.z) * cw * s0.z;
        gs.w = (acc[i][3] + bf0.w) * cw * s0.w;
        ge.x = (acc[i][4] + bf1.x) * cw * s1.x;
        ge.y = (acc[i][5] + bf1.y) * cw * s1.y;
        ge.z = (acc[i][6] + bf1.z) * cw * s1.z;
        ge.w = (acc[i][7] + bf1.w) * cw * s1.w;
        ms.x = (acc[i][8] + bf2.x) * cw * s2.x;
        ms.y = (acc[i][9] + bf2.y) * cw * s2.y;
        ms.z = (acc[i][10]+ bf2.z) * cw * s2.z;
        ms.w = (acc[i][11]+ bf2.w) * cw * s2.w;

        red_add4(out_s + (size_t)dst * FDIM + cb, ms);

        const __half* nvp = nvec + (size_t)src * F3 + cb;
        float u0 = s_unit[0][e], u1 = s_unit[1][e], u2 = s_unit[2][e];

        float4 v, m;
        v = ld_half4(nvp);
        m.x = v.x * gs.x + ge.x * u0;  m.y = v.y * gs.y + ge.y * u0;
        m.z = v.z * gs.z + ge.z * u0;  m.w = v.w * gs.w + ge.w * u0;
        red_add4(out_v + (size_t)dst * F3 + cb, m);

        v = ld_half4(nvp + FDIM);
        m.x = v.x * gs.x + ge.x * u1;  m.y = v.y * gs.y + ge.y * u1;
        m.z = v.z * gs.z + ge.z * u1;  m.w = v.w * gs.w + ge.w * u1;
        red_add4(out_v + (size_t)dst * F3 + FDIM + cb, m);

        v = ld_half4(nvp + 2 * FDIM);
        m.x = v.x * gs.x + ge.x * u2;  m.y = v.y * gs.y + ge.y * u2;
        m.z = v.z * gs.z + ge.z * u2;  m.w = v.w * gs.w + ge.w * u2;
        red_add4(out_v + (size_t)dst * F3 + 2 * FDIM + cb, m);
    }
}

// ---------------------------------------------------------------------------
extern "C" void kernel_launch(void* const* d_in, const int* in_sizes, int n_in,
                              void* d_out, int out_size) {
    const int2*  eidx  = (const int2*) d_in[0];
    const float* edist = (const float*)d_in[1];
    const float* ediff = (const float*)d_in[2];
    const float* ns    = (const float*)d_in[3];
    const float* nv    = (const float*)d_in[4];
    const float* Wf    = (const float*)d_in[5];
    const float* bf    = (const float*)d_in[6];
    const float* W1    = (const float*)d_in[7];
    const float* b1    = (const float*)d_in[8];
    const float* W2    = (const float*)d_in[9];
    const float* b2    = (const float*)d_in[10];
    float* out = (float*)d_out;

    float  *h_ptr;
    __half *so_ptr, *nvh_ptr;
    cudaGetSymbolAddress((void**)&h_ptr,   g_h);
    cudaGetSymbolAddress((void**)&so_ptr,  g_so);
    cudaGetSymbolAddress((void**)&nvh_ptr, g_nvh);

    int tot4 = (NNODES * FDIM + NNODES * F3) / 4;
    copy_init_kernel<<<(tot4 + 255) / 256, 256>>>(
        (const float4*)ns, (const float4*)nv, (float4*)out);

    int nv4 = NNODES * F3 / 4;
    f2h_kernel<<<(nv4 + 255) / 256, 256>>>(
        (const float4*)nv, (uint2*)nvh_ptr, nv4);

    gemm_kernel<true, false><<<dim3((NNODES + 63) / 64, FDIM / 64), 256>>>(
        ns, W1, b1, h_ptr, NNODES, FDIM, FDIM);

    gemm_kernel<false, true><<<dim3((NNODES + 63) / 64, F3 / 64), 256>>>(
        h_ptr, W2, b2, so_ptr, NNODES, F3, FDIM);

    edge_kernel<<<NEDGES / 32, 256>>>(
        eidx, edist, ediff, Wf, bf, nvh_ptr, so_ptr,
        out, out + (size_t)NNODES * FDIM);
}

// round 4
// speedup vs baseline: 9.0284x; 1.2579x over previous
#include <cuda_runtime.h>
#include <cuda_fp16.h>
#include <math.h>

#define NNODES 50000
#define NEDGES 400000
#define FDIM   128
#define F3     384
#define NB     20
#define EPB    128

__device__ float  g_h [(size_t)NNODES * FDIM];   // silu(ns@W1+b1)
__device__ __half g_so[(size_t)NNODES * F3];     // scalar_out (fp16)
__device__ __half g_nvh[(size_t)NNODES * F3];    // node_vector (fp16)

// ---------------------------------------------------------------------------
// out = concat(node_scalar, node_vector); also emit node_vector as fp16
// ---------------------------------------------------------------------------
__global__ void copy_init_kernel(const float4* __restrict__ ns,
                                 const float4* __restrict__ nv,
                                 float4* __restrict__ out,
                                 uint2* __restrict__ nvh) {
    const int NS4 = NNODES * FDIM / 4;
    const int NT4 = NS4 + NNODES * F3 / 4;
    int i = blockIdx.x * blockDim.x + threadIdx.x;
    if (i >= NT4) return;
    if (i < NS4) {
        out[i] = ns[i];
    } else {
        float4 v = nv[i - NS4];
        out[i] = v;
        __half2 h0 = __floats2half2_rn(v.x, v.y);
        __half2 h1 = __floats2half2_rn(v.z, v.w);
        nvh[i - NS4] = make_uint2(*(unsigned*)&h0, *(unsigned*)&h1);
    }
}

__device__ __forceinline__ float4 ld_half4(const __half* p) {
    uint2 u = *(const uint2*)p;
    __half2 h0 = *reinterpret_cast<__half2*>(&u.x);
    __half2 h1 = *reinterpret_cast<__half2*>(&u.y);
    float2 f0 = __half22float2(h0), f1 = __half22float2(h1);
    return make_float4(f0.x, f0.y, f1.x, f1.y);
}

// ---------------------------------------------------------------------------
// C[M,N] = act(A[M,K] @ W[K,N] + bias)
// BM=128, BN=64, BK=16, 256 threads, 8x4 per-thread tile
// ---------------------------------------------------------------------------
template<bool SILU, bool HALF_OUT>
__global__ __launch_bounds__(256)
void gemm_kernel(const float* __restrict__ A, const float* __restrict__ W,
                 const float* __restrict__ bias, void* __restrict__ Cv,
                 int M, int N, int K)
{
    const int BM = 128, BN = 64, BK = 16;
    __shared__ float As[BK][BM];
    __shared__ float Bs[BK][BN];

    int t  = threadIdx.x;
    int m0 = blockIdx.x * BM;
    int n0 = blockIdx.y * BN;
    int ty = t >> 4, tx = t & 15;     // 16x16 threads; ty->8 rows, tx->4 cols

    int ar = t >> 1;                  // 0..127  (A row in tile)
    int ak = (t & 1) << 3;            // 0 or 8  (A k-offset, 2 float4)
    int bk = t >> 4;                  // 0..15
    int bn = (t & 15) << 2;           // 0..60

    float acc[8][4];
#pragma unroll
    for (int i = 0; i < 8; i++)
#pragma unroll
        for (int j = 0; j < 4; j++) acc[i][j] = 0.0f;

    for (int k0 = 0; k0 < K; k0 += BK) {
        float4 av0 = make_float4(0.f,0.f,0.f,0.f);
        float4 av1 = make_float4(0.f,0.f,0.f,0.f);
        if (m0 + ar < M) {
            const float* ap = A + (size_t)(m0 + ar) * K + k0 + ak;
            av0 = *(const float4*)ap;
            av1 = *(const float4*)(ap + 4);
        }
        As[ak + 0][ar] = av0.x; As[ak + 1][ar] = av0.y;
        As[ak + 2][ar] = av0.z; As[ak + 3][ar] = av0.w;
        As[ak + 4][ar] = av1.x; As[ak + 5][ar] = av1.y;
        As[ak + 6][ar] = av1.z; As[ak + 7][ar] = av1.w;
        *(float4*)&Bs[bk][bn] = *(const float4*)(W + (size_t)(k0 + bk) * N + n0 + bn);
        __syncthreads();
#pragma unroll
        for (int k = 0; k < BK; k++) {
            float4 a0 = *(float4*)&As[k][ty << 3];
            float4 a1 = *(float4*)&As[k][(ty << 3) + 4];
            float4 b4 = *(float4*)&Bs[k][tx << 2];
            float a[8] = {a0.x,a0.y,a0.z,a0.w,a1.x,a1.y,a1.z,a1.w};
            float b[4] = {b4.x,b4.y,b4.z,b4.w};
#pragma unroll
            for (int i = 0; i < 8; i++)
#pragma unroll
                for (int j = 0; j < 4; j++) acc[i][j] += a[i] * b[j];
        }
        __syncthreads();
    }

    float4 bb = *(const float4*)(bias + n0 + (tx << 2));
    float bv[4] = {bb.x, bb.y, bb.z, bb.w};
#pragma unroll
    for (int i = 0; i < 8; i++) {
        int m = m0 + (ty << 3) + i;
        if (m < M) {
            float v[4];
#pragma unroll
            for (int j = 0; j < 4; j++) {
                float x = acc[i][j] + bv[j];
                if (SILU) x = x / (1.0f + expf(-x));
                v[j] = x;
            }
            if (HALF_OUT) {
                __half2 h0 = __floats2half2_rn(v[0], v[1]);
                __half2 h1 = __floats2half2_rn(v[2], v[3]);
                uint2 o = make_uint2(*(unsigned*)&h0, *(unsigned*)&h1);
                *(uint2*)((__half*)Cv + (size_t)m * N + n0 + (tx << 2)) = o;
            } else {
                float4 o = make_float4(v[0], v[1], v[2], v[3]);
                *(float4*)((float*)Cv + (size_t)m * N + n0 + (tx << 2)) = o;
            }
        }
    }
}

// ---------------------------------------------------------------------------
__device__ __forceinline__ void red_add4(float* p, float4 v) {
    asm volatile("red.global.add.v4.f32 [%0], {%1, %2, %3, %4};"
                 :: "l"(p), "f"(v.x), "f"(v.y), "f"(v.z), "f"(v.w)
                 : "memory");
}

// ---------------------------------------------------------------------------
// Edge kernel: 128 edges / block of 256 threads, 4 sequential passes of the
// round-1 32-edge register tile (#pragma unroll 1 -> acc regs reused, no
// spills). W_filter staged once per 128 edges (4x less L2 traffic).
// ---------------------------------------------------------------------------
__global__ __launch_bounds__(256)
void edge_kernel(const int2*   __restrict__ eidx,
                 const float*  __restrict__ edist,
                 const float*  __restrict__ ediff,
                 const float*  __restrict__ Wf,      // [NB][384] fp32
                 const float*  __restrict__ bf,      // [384]
                 const __half* __restrict__ nvec,    // [N,3,128] fp16
                 const __half* __restrict__ so,      // [N,384] fp16
                 float* __restrict__ out_s,          // [N,128]
                 float* __restrict__ out_v)          // [N,3,128]
{
    __shared__ float s_Wf[NB * F3];          // 30720 B
    __shared__ float s_basis[EPB * NB];      // 10240 B
    __shared__ float s_cut[EPB];
    __shared__ int   s_src[EPB], s_dst[EPB];
    __shared__ float s_unit[3][EPB];
    __shared__ float s_d[EPB];

    const float PI_C = 0.628318530717958648f;   // pi / 5

    int t  = threadIdx.x;
    int e0 = blockIdx.x * EPB;

    for (int i = t; i < NB * F3 / 4; i += 256)
        ((float4*)s_Wf)[i] = ((const float4*)Wf)[i];

    if (t < EPB) {
        int e = e0 + t;
        int2 ei = eidx[e];
        s_dst[t] = ei.x;
        s_src[t] = ei.y;
        float d = edist[e];
        s_d[t] = d;
        s_cut[t] = (d < 5.0f) ? 0.5f * (cosf(d * PI_C) + 1.0f) : 0.0f;
        float inv = 1.0f / d;
        s_unit[0][t] = ediff[e * 3 + 0] * inv;
        s_unit[1][t] = ediff[e * 3 + 1] * inv;
        s_unit[2][t] = ediff[e * 3 + 2] * inv;
    }
    __syncthreads();

    for (int i = t; i < EPB * NB; i += 256) {
        int e = i / NB, n = i % NB;
        float d = s_d[e];
        float x = d * (float)(n + 1) * PI_C;
        x -= 6.2831853071795865f * rintf(x * 0.15915494309189534f);
        s_basis[i] = sinf(x) / d;
    }
    __syncthreads();

    int cg = t & 31;
    int eg = t >> 5;           // warp 0..7
    int cb = cg << 2;

    float4 bf0 = *(const float4*)&bf[cb];
    float4 bf1 = *(const float4*)&bf[FDIM + cb];
    float4 bf2 = *(const float4*)&bf[2 * FDIM + cb];

#pragma unroll 1
    for (int pass = 0; pass < EPB / 32; pass++) {
        int egg = pass * 8 + eg;           // edge group 0..31 (4 edges each)

        float acc[4][12];
#pragma unroll
        for (int i = 0; i < 4; i++)
#pragma unroll
            for (int j = 0; j < 12; j++) acc[i][j] = 0.0f;

        const float* bas = &s_basis[(egg << 2) * NB];
#pragma unroll
        for (int k = 0; k < NB; k++) {
            float be[4];
#pragma unroll
            for (int i = 0; i < 4; i++) be[i] = bas[i * NB + k];
            float4 w0 = *(float4*)&s_Wf[k * F3 + cb];
            float4 w1 = *(float4*)&s_Wf[k * F3 + FDIM + cb];
            float4 w2 = *(float4*)&s_Wf[k * F3 + 2 * FDIM + cb];
#pragma unroll
            for (int i = 0; i < 4; i++) {
                acc[i][0] += be[i] * w0.x; acc[i][1] += be[i] * w0.y;
                acc[i][2] += be[i] * w0.z; acc[i][3] += be[i] * w0.w;
                acc[i][4] += be[i] * w1.x; acc[i][5] += be[i] * w1.y;
                acc[i][6] += be[i] * w1.z; acc[i][7] += be[i] * w1.w;
                acc[i][8] += be[i] * w2.x; acc[i][9] += be[i] * w2.y;
                acc[i][10]+= be[i] * w2.z; acc[i][11]+= be[i] * w2.w;
            }
        }

#pragma unroll
        for (int i = 0; i < 4; i++) {
            int e   = (egg << 2) + i;
            int src = s_src[e];
            int dst = s_dst[e];
            float cw = s_cut[e];

            const __half* sor = so + (size_t)src * F3 + cb;
            float4 s0 = ld_half4(sor);
            float4 s1 = ld_half4(sor + FDIM);
            float4 s2 = ld_half4(sor + 2 * FDIM);

            float4 gs, ge, ms;
            gs.x = (acc[i][0] + bf0.x) * cw * s0.x;
            gs.y = (acc[i][1] + bf0.y) * cw * s0.y;
            gs.z = (acc[i][2] + bf0.z) * cw * s0.z;
            gs.w = (acc[i][3] + bf0.w) * cw * s0.w;
            ge.x = (acc[i][4] + bf1.x) * cw * s1.x;
            ge.y = (acc[i][5] + bf1.y) * cw * s1.y;
            ge.z = (acc[i][6] + bf1.z) * cw * s1.z;
            ge.w = (acc[i][7] + bf1.w) * cw * s1.w;
            ms.x = (acc[i][8] + bf2.x) * cw * s2.x;
            ms.y = (acc[i][9] + bf2.y) * cw * s2.y;
            ms.z = (acc[i][10]+ bf2.z) * cw * s2.z;
            ms.w = (acc[i][11]+ bf2.w) * cw * s2.w;

            red_add4(out_s + (size_t)dst * FDIM + cb, ms);

            const __half* nvp = nvec + (size_t)src * F3 + cb;
            float u0 = s_unit[0][e], u1 = s_unit[1][e], u2 = s_unit[2][e];

            float4 v, m;
            v = ld_half4(nvp);
            m.x = v.x * gs.x + ge.x * u0;  m.y = v.y * gs.y + ge.y * u0;
            m.z = v.z * gs.z + ge.z * u0;  m.w = v.w * gs.w + ge.w * u0;
            red_add4(out_v + (size_t)dst * F3 + cb, m);

            v = ld_half4(nvp + FDIM);
            m.x = v.x * gs.x + ge.x * u1;  m.y = v.y * gs.y + ge.y * u1;
            m.z = v.z * gs.z + ge.z * u1;  m.w = v.w * gs.w + ge.w * u1;
            red_add4(out_v + (size_t)dst * F3 + FDIM + cb, m);

            v = ld_half4(nvp + 2 * FDIM);
            m.x = v.x * gs.x + ge.x * u2;  m.y = v.y * gs.y + ge.y * u2;
            m.z = v.z * gs.z + ge.z * u2;  m.w = v.w * gs.w + ge.w * u2;
            red_add4(out_v + (size_t)dst * F3 + 2 * FDIM + cb, m);
        }
    }
}

// ---------------------------------------------------------------------------
extern "C" void kernel_launch(void* const* d_in, const int* in_sizes, int n_in,
                              void* d_out, int out_size) {
    const int2*  eidx  = (const int2*) d_in[0];
    const float* edist = (const float*)d_in[1];
    const float* ediff = (const float*)d_in[2];
    const float* ns    = (const float*)d_in[3];
    const float* nv    = (const float*)d_in[4];
    const float* Wf    = (const float*)d_in[5];
    const float* bf    = (const float*)d_in[6];
    const float* W1    = (const float*)d_in[7];
    const float* b1    = (const float*)d_in[8];
    const float* W2    = (const float*)d_in[9];
    const float* b2    = (const float*)d_in[10];
    float* out = (float*)d_out;

    float  *h_ptr;
    __half *so_ptr, *nvh_ptr;
    cudaGetSymbolAddress((void**)&h_ptr,   g_h);
    cudaGetSymbolAddress((void**)&so_ptr,  g_so);
    cudaGetSymbolAddress((void**)&nvh_ptr, g_nvh);

    int tot4 = (NNODES * FDIM + NNODES * F3) / 4;
    copy_init_kernel<<<(tot4 + 255) / 256, 256>>>(
        (const float4*)ns, (const float4*)nv, (float4*)out, (uint2*)nvh_ptr);

    gemm_kernel<true, false><<<dim3((NNODES + 127) / 128, FDIM / 64), 256>>>(
        ns, W1, b1, h_ptr, NNODES, FDIM, FDIM);

    gemm_kernel<false, true><<<dim3((NNODES + 127) / 128, F3 / 64), 256>>>(
        h_ptr, W2, b2, so_ptr, NNODES, F3, FDIM);

    edge_kernel<<<NEDGES / EPB, 256>>>(
        eidx, edist, ediff, Wf, bf, nvh_ptr, so_ptr,
        out, out + (size_t)NNODES * FDIM);
}

// round 5
// speedup vs baseline: 9.0419x; 1.0015x over previous
#include <cuda_runtime.h>
#include <cuda_fp16.h>
#include <math.h>

#define NNODES 50000
#define NEDGES 400000
#define FDIM   128
#define F3     384
#define NB     20
#define EPB    128

__device__ float  g_h [(size_t)NNODES * FDIM];   // silu(ns@W1+b1)
__device__ __half g_so[(size_t)NNODES * F3];     // scalar_out (fp16)
__device__ __half g_nvh[(size_t)NNODES * F3];    // node_vector (fp16)

// ---------------------------------------------------------------------------
// out = concat(node_scalar, node_vector); also emit node_vector as fp16
// ---------------------------------------------------------------------------
__global__ void copy_init_kernel(const float4* __restrict__ ns,
                                 const float4* __restrict__ nv,
                                 float4* __restrict__ out,
                                 uint2* __restrict__ nvh) {
    const int NS4 = NNODES * FDIM / 4;
    const int NT4 = NS4 + NNODES * F3 / 4;
    int i = blockIdx.x * blockDim.x + threadIdx.x;
    if (i >= NT4) return;
    if (i < NS4) {
        out[i] = ns[i];
    } else {
        float4 v = nv[i - NS4];
        out[i] = v;
        __half2 h0 = __floats2half2_rn(v.x, v.y);
        __half2 h1 = __floats2half2_rn(v.z, v.w);
        nvh[i - NS4] = make_uint2(*(unsigned*)&h0, *(unsigned*)&h1);
    }
}

__device__ __forceinline__ float4 ld_half4(const __half* p) {
    uint2 u = *(const uint2*)p;
    __half2 h0 = *reinterpret_cast<__half2*>(&u.x);
    __half2 h1 = *reinterpret_cast<__half2*>(&u.y);
    float2 f0 = __half22float2(h0), f1 = __half22float2(h1);
    return make_float4(f0.x, f0.y, f1.x, f1.y);
}

// ---------------------------------------------------------------------------
// C[M,N] = act(A[M,K] @ W[K,N] + bias)
// BM=128, BN=64, BK=16, 256 threads, 8x4 per-thread tile
// ---------------------------------------------------------------------------
template<bool SILU, bool HALF_OUT>
__global__ __launch_bounds__(256)
void gemm_kernel(const float* __restrict__ A, const float* __restrict__ W,
                 const float* __restrict__ bias, void* __restrict__ Cv,
                 int M, int N, int K)
{
    const int BM = 128, BN = 64, BK = 16;
    __shared__ float As[BK][BM];
    __shared__ float Bs[BK][BN];

    int t  = threadIdx.x;
    int m0 = blockIdx.x * BM;
    int n0 = blockIdx.y * BN;
    int ty = t >> 4, tx = t & 15;     // 16x16 threads; ty->8 rows, tx->4 cols

    int ar = t >> 1;                  // 0..127  (A row in tile)
    int ak = (t & 1) << 3;            // 0 or 8  (A k-offset, 2 float4)
    int bk = t >> 4;                  // 0..15
    int bn = (t & 15) << 2;           // 0..60

    float acc[8][4];
#pragma unroll
    for (int i = 0; i < 8; i++)
#pragma unroll
        for (int j = 0; j < 4; j++) acc[i][j] = 0.0f;

    for (int k0 = 0; k0 < K; k0 += BK) {
        float4 av0 = make_float4(0.f,0.f,0.f,0.f);
        float4 av1 = make_float4(0.f,0.f,0.f,0.f);
        if (m0 + ar < M) {
            const float* ap = A + (size_t)(m0 + ar) * K + k0 + ak;
            av0 = *(const float4*)ap;
            av1 = *(const float4*)(ap + 4);
        }
        As[ak + 0][ar] = av0.x; As[ak + 1][ar] = av0.y;
        As[ak + 2][ar] = av0.z; As[ak + 3][ar] = av0.w;
        As[ak + 4][ar] = av1.x; As[ak + 5][ar] = av1.y;
        As[ak + 6][ar] = av1.z; As[ak + 7][ar] = av1.w;
        *(float4*)&Bs[bk][bn] = *(const float4*)(W + (size_t)(k0 + bk) * N + n0 + bn);
        __syncthreads();
#pragma unroll
        for (int k = 0; k < BK; k++) {
            float4 a0 = *(float4*)&As[k][ty << 3];
            float4 a1 = *(float4*)&As[k][(ty << 3) + 4];
            float4 b4 = *(float4*)&Bs[k][tx << 2];
            float a[8] = {a0.x,a0.y,a0.z,a0.w,a1.x,a1.y,a1.z,a1.w};
            float b[4] = {b4.x,b4.y,b4.z,b4.w};
#pragma unroll
            for (int i = 0; i < 8; i++)
#pragma unroll
                for (int j = 0; j < 4; j++) acc[i][j] += a[i] * b[j];
        }
        __syncthreads();
    }

    float4 bb = *(const float4*)(bias + n0 + (tx << 2));
    float bv[4] = {bb.x, bb.y, bb.z, bb.w};
#pragma unroll
    for (int i = 0; i < 8; i++) {
        int m = m0 + (ty << 3) + i;
        if (m < M) {
            float v[4];
#pragma unroll
            for (int j = 0; j < 4; j++) {
                float x = acc[i][j] + bv[j];
                if (SILU) x = x / (1.0f + expf(-x));
                v[j] = x;
            }
            if (HALF_OUT) {
                __half2 h0 = __floats2half2_rn(v[0], v[1]);
                __half2 h1 = __floats2half2_rn(v[2], v[3]);
                uint2 o = make_uint2(*(unsigned*)&h0, *(unsigned*)&h1);
                *(uint2*)((__half*)Cv + (size_t)m * N + n0 + (tx << 2)) = o;
            } else {
                float4 o = make_float4(v[0], v[1], v[2], v[3]);
                *(float4*)((float*)Cv + (size_t)m * N + n0 + (tx << 2)) = o;
            }
        }
    }
}

// ---------------------------------------------------------------------------
__device__ __forceinline__ void red_add4(float* p, float4 v) {
    asm volatile("red.global.add.v4.f32 [%0], {%1, %2, %3, %4};"
                 :: "l"(p), "f"(v.x), "f"(v.y), "f"(v.z), "f"(v.w)
                 : "memory");
}

// ---------------------------------------------------------------------------
// Edge kernel: 128 edges / block of 256 threads, 4 sequential passes of the
// round-1 32-edge register tile (#pragma unroll 1 -> acc regs reused, no
// spills). W_filter staged once per 128 edges (4x less L2 traffic).
// ---------------------------------------------------------------------------
__global__ __launch_bounds__(256)
void edge_kernel(const int2*   __restrict__ eidx,
                 const float*  __restrict__ edist,
                 const float*  __restrict__ ediff,
                 const float*  __restrict__ Wf,      // [NB][384] fp32
                 const float*  __restrict__ bf,      // [384]
                 const __half* __restrict__ nvec,    // [N,3,128] fp16
                 const __half* __restrict__ so,      // [N,384] fp16
                 float* __restrict__ out_s,          // [N,128]
                 float* __restrict__ out_v)          // [N,3,128]
{
    __shared__ float s_Wf[NB * F3];          // 30720 B
    __shared__ float s_basis[EPB * NB];      // 10240 B
    __shared__ float s_cut[EPB];
    __shared__ int   s_src[EPB], s_dst[EPB];
    __shared__ float s_unit[3][EPB];
    __shared__ float s_d[EPB];

    const float PI_C = 0.628318530717958648f;   // pi / 5

    int t  = threadIdx.x;
    int e0 = blockIdx.x * EPB;

    for (int i = t; i < NB * F3 / 4; i += 256)
        ((float4*)s_Wf)[i] = ((const float4*)Wf)[i];

    if (t < EPB) {
        int e = e0 + t;
        int2 ei = eidx[e];
        s_dst[t] = ei.x;
        s_src[t] = ei.y;
        float d = edist[e];
        s_d[t] = d;
        s_cut[t] = (d < 5.0f) ? 0.5f * (cosf(d * PI_C) + 1.0f) : 0.0f;
        float inv = 1.0f / d;
        s_unit[0][t] = ediff[e * 3 + 0] * inv;
        s_unit[1][t] = ediff[e * 3 + 1] * inv;
        s_unit[2][t] = ediff[e * 3 + 2] * inv;
    }
    __syncthreads();

    for (int i = t; i < EPB * NB; i += 256) {
        int e = i / NB, n = i % NB;
        float d = s_d[e];
        float x = d * (float)(n + 1) * PI_C;
        x -= 6.2831853071795865f * rintf(x * 0.15915494309189534f);
        s_basis[i] = sinf(x) / d;
    }
    __syncthreads();

    int cg = t & 31;
    int eg = t >> 5;           // warp 0..7
    int cb = cg << 2;

    float4 bf0 = *(const float4*)&bf[cb];
    float4 bf1 = *(const float4*)&bf[FDIM + cb];
    float4 bf2 = *(const float4*)&bf[2 * FDIM + cb];

#pragma unroll 1
    for (int pass = 0; pass < EPB / 32; pass++) {
        int egg = pass * 8 + eg;           // edge group 0..31 (4 edges each)

        float acc[4][12];
#pragma unroll
        for (int i = 0; i < 4; i++)
#pragma unroll
            for (int j = 0; j < 12; j++) acc[i][j] = 0.0f;

        const float* bas = &s_basis[(egg << 2) * NB];
#pragma unroll
        for (int k = 0; k < NB; k++) {
            float be[4];
#pragma unroll
            for (int i = 0; i < 4; i++) be[i] = bas[i * NB + k];
            float4 w0 = *(float4*)&s_Wf[k * F3 + cb];
            float4 w1 = *(float4*)&s_Wf[k * F3 + FDIM + cb];
            float4 w2 = *(float4*)&s_Wf[k * F3 + 2 * FDIM + cb];
#pragma unroll
            for (int i = 0; i < 4; i++) {
                acc[i][0] += be[i] * w0.x; acc[i][1] += be[i] * w0.y;
                acc[i][2] += be[i] * w0.z; acc[i][3] += be[i] * w0.w;
                acc[i][4] += be[i] * w1.x; acc[i][5] += be[i] * w1.y;
                acc[i][6] += be[i] * w1.z; acc[i][7] += be[i] * w1.w;
                acc[i][8] += be[i] * w2.x; acc[i][9] += be[i] * w2.y;
                acc[i][10]+= be[i] * w2.z; acc[i][11]+= be[i] * w2.w;
            }
        }

#pragma unroll
        for (int i = 0; i < 4; i++) {
            int e   = (egg << 2) + i;
            int src = s_src[e];
            int dst = s_dst[e];
            float cw = s_cut[e];

            const __half* sor = so + (size_t)src * F3 + cb;
            float4 s0 = ld_half4(sor);
            float4 s1 = ld_half4(sor + FDIM);
            float4 s2 = ld_half4(sor + 2 * FDIM);

            float4 gs, ge, ms;
            gs.x = (acc[i][0] + bf0.x) * cw * s0.x;
            gs.y = (acc[i][1] + bf0.y) * cw * s0.y;
            gs.z = (acc[i][2] + bf0.z) * cw * s0.z;
            gs.w = (acc[i][3] + bf0.w) * cw * s0.w;
            ge.x = (acc[i][4] + bf1.x) * cw * s1.x;
            ge.y = (acc[i][5] + bf1.y) * cw * s1.y;
            ge.z = (acc[i][6] + bf1.z) * cw * s1.z;
            ge.w = (acc[i][7] + bf1.w) * cw * s1.w;
            ms.x = (acc[i][8] + bf2.x) * cw * s2.x;
            ms.y = (acc[i][9] + bf2.y) * cw * s2.y;
            ms.z = (acc[i][10]+ bf2.z) * cw * s2.z;
            ms.w = (acc[i][11]+ bf2.w) * cw * s2.w;

            red_add4(out_s + (size_t)dst * FDIM + cb, ms);

            const __half* nvp = nvec + (size_t)src * F3 + cb;
            float u0 = s_unit[0][e], u1 = s_unit[1][e], u2 = s_unit[2][e];

            float4 v, m;
            v = ld_half4(nvp);
            m.x = v.x * gs.x + ge.x * u0;  m.y = v.y * gs.y + ge.y * u0;
            m.z = v.z * gs.z + ge.z * u0;  m.w = v.w * gs.w + ge.w * u0;
            red_add4(out_v + (size_t)dst * F3 + cb, m);

            v = ld_half4(nvp + FDIM);
            m.x = v.x * gs.x + ge.x * u1;  m.y = v.y * gs.y + ge.y * u1;
            m.z = v.z * gs.z + ge.z * u1;  m.w = v.w * gs.w + ge.w * u1;
            red_add4(out_v + (size_t)dst * F3 + FDIM + cb, m);

            v = ld_half4(nvp + 2 * FDIM);
            m.x = v.x * gs.x + ge.x * u2;  m.y = v.y * gs.y + ge.y * u2;
            m.z = v.z * gs.z + ge.z * u2;  m.w = v.w * gs.w + ge.w * u2;
            red_add4(out_v + (size_t)dst * F3 + 2 * FDIM + cb, m);
        }
    }
}

// ---------------------------------------------------------------------------
extern "C" void kernel_launch(void* const* d_in, const int* in_sizes, int n_in,
                              void* d_out, int out_size) {
    const int2*  eidx  = (const int2*) d_in[0];
    const float* edist = (const float*)d_in[1];
    const float* ediff = (const float*)d_in[2];
    const float* ns    = (const float*)d_in[3];
    const float* nv    = (const float*)d_in[4];
    const float* Wf    = (const float*)d_in[5];
    const float* bf    = (const float*)d_in[6];
    const float* W1    = (const float*)d_in[7];
    const float* b1    = (const float*)d_in[8];
    const float* W2    = (const float*)d_in[9];
    const float* b2    = (const float*)d_in[10];
    float* out = (float*)d_out;

    float  *h_ptr;
    __half *so_ptr, *nvh_ptr;
    cudaGetSymbolAddress((void**)&h_ptr,   g_h);
    cudaGetSymbolAddress((void**)&so_ptr,  g_so);
    cudaGetSymbolAddress((void**)&nvh_ptr, g_nvh);

    int tot4 = (NNODES * FDIM + NNODES * F3) / 4;
    copy_init_kernel<<<(tot4 + 255) / 256, 256>>>(
        (const float4*)ns, (const float4*)nv, (float4*)out, (uint2*)nvh_ptr);

    gemm_kernel<true, false><<<dim3((NNODES + 127) / 128, FDIM / 64), 256>>>(
        ns, W1, b1, h_ptr, NNODES, FDIM, FDIM);

    gemm_kernel<false, true><<<dim3((NNODES + 127) / 128, F3 / 64), 256>>>(
        h_ptr, W2, b2, so_ptr, NNODES, F3, FDIM);

    edge_kernel<<<NEDGES / EPB, 256>>>(
        eidx, edist, ediff, Wf, bf, nvh_ptr, so_ptr,
        out, out + (size_t)NNODES * FDIM);
}

// round 6
// speedup vs baseline: 10.9551x; 1.2116x over previous
#include <cuda_runtime.h>
#include <cuda_fp16.h>
#include <mma.h>
#include <math.h>

using namespace nvcuda;

#define NNODES 50000
#define NEDGES 400000
#define FDIM   128
#define F3     384
#define NB     20
#define EPB    128

__device__ __half g_nsh[(size_t)NNODES * FDIM];  // node_scalar fp16
__device__ __half g_h [(size_t)NNODES * FDIM];   // silu(ns@W1+b1) fp16
__device__ __half g_so[(size_t)NNODES * F3];     // scalar_out fp16
__device__ __half g_nvh[(size_t)NNODES * F3];    // node_vector fp16
__device__ __half g_W1h[FDIM * FDIM];
__device__ __half g_W2h[FDIM * F3];

// ---------------------------------------------------------------------------
// out = concat(node_scalar, node_vector); emit fp16 copies of both
// ---------------------------------------------------------------------------
__global__ void copy_init_kernel(const float4* __restrict__ ns,
                                 const float4* __restrict__ nv,
                                 float4* __restrict__ out,
                                 uint2* __restrict__ nsh,
                                 uint2* __restrict__ nvh) {
    const int NS4 = NNODES * FDIM / 4;
    const int NT4 = NS4 + NNODES * F3 / 4;
    int i = blockIdx.x * blockDim.x + threadIdx.x;
    if (i >= NT4) return;
    if (i < NS4) {
        float4 v = ns[i];
        out[i] = v;
        __half2 h0 = __floats2half2_rn(v.x, v.y);
        __half2 h1 = __floats2half2_rn(v.z, v.w);
        nsh[i] = make_uint2(*(unsigned*)&h0, *(unsigned*)&h1);
    } else {
        float4 v = nv[i - NS4];
        out[i] = v;
        __half2 h0 = __floats2half2_rn(v.x, v.y);
        __half2 h1 = __floats2half2_rn(v.z, v.w);
        nvh[i - NS4] = make_uint2(*(unsigned*)&h0, *(unsigned*)&h1);
    }
}

// fp32 -> fp16, generic small arrays (n divisible by 4)
__global__ void f2h_small_kernel(const float4* __restrict__ in,
                                 uint2* __restrict__ out, int n4) {
    int i = blockIdx.x * blockDim.x + threadIdx.x;
    if (i < n4) {
        float4 v = in[i];
        __half2 h0 = __floats2half2_rn(v.x, v.y);
        __half2 h1 = __floats2half2_rn(v.z, v.w);
        out[i] = make_uint2(*(unsigned*)&h0, *(unsigned*)&h1);
    }
}

__device__ __forceinline__ float4 ld_half4(const __half* p) {
    uint2 u = *(const uint2*)p;
    __half2 h0 = *reinterpret_cast<__half2*>(&u.x);
    __half2 h1 = *reinterpret_cast<__half2*>(&u.y);
    float2 f0 = __half22float2(h0), f1 = __half22float2(h1);
    return make_float4(f0.x, f0.y, f1.x, f1.y);
}

// ---------------------------------------------------------------------------
// Tensor-core GEMM: C[M,N] = act(A[M,128] @ W[128,N] + bias), fp16 in/out,
// fp32 accumulate. BM=128, BN=64, BK=32; 8 warps in 4x2 grid, 32x32 per warp.
// ---------------------------------------------------------------------------
template<bool SILU>
__global__ __launch_bounds__(256)
void hgemm_kernel(const __half* __restrict__ A, const __half* __restrict__ W,
                  const float* __restrict__ bias, __half* __restrict__ C,
                  int M, int N)
{
    const int K = 128, BM = 128, BK = 32;
    const int LDA = 48, LDB = 72, LDE = 36;
    __shared__ __half As[BM * LDA];        // 12288 B
    __shared__ __half Bs[BK * LDB];        // 4608 B
    __shared__ float  Es[8][16 * LDE];     // 18432 B

    int t = threadIdx.x;
    int warp = t >> 5, lane = t & 31;
    int wm = warp >> 1, wn = warp & 1;
    int m0 = blockIdx.x * BM;
    int n0 = blockIdx.y * 64;

    wmma::fragment<wmma::accumulator, 16, 16, 16, float> acc[2][2];
#pragma unroll
    for (int i = 0; i < 2; i++)
#pragma unroll
        for (int j = 0; j < 2; j++) wmma::fill_fragment(acc[i][j], 0.0f);

    // load indices
    int arow = t >> 1, acolh = (t & 1) << 4;       // A: 2 x uint4 per thread
    int brow = t >> 3, bcolh = (t & 7) << 3;       // B: 1 x uint4 per thread

#pragma unroll 1
    for (int k0 = 0; k0 < K; k0 += BK) {
        uint4 v0 = make_uint4(0,0,0,0), v1 = v0;
        if (m0 + arow < M) {
            const __half* ap = A + (size_t)(m0 + arow) * K + k0 + acolh;
            v0 = *(const uint4*)ap;
            v1 = *(const uint4*)(ap + 8);
        }
        *(uint4*)(As + arow * LDA + acolh)     = v0;
        *(uint4*)(As + arow * LDA + acolh + 8) = v1;
        *(uint4*)(Bs + brow * LDB + bcolh) =
            *(const uint4*)(W + (size_t)(k0 + brow) * N + n0 + bcolh);
        __syncthreads();

#pragma unroll
        for (int kk = 0; kk < BK; kk += 16) {
            wmma::fragment<wmma::matrix_a, 16,16,16, __half, wmma::row_major> af[2];
            wmma::fragment<wmma::matrix_b, 16,16,16, __half, wmma::row_major> bf[2];
#pragma unroll
            for (int i = 0; i < 2; i++)
                wmma::load_matrix_sync(af[i], As + (wm * 32 + i * 16) * LDA + kk, LDA);
#pragma unroll
            for (int j = 0; j < 2; j++)
                wmma::load_matrix_sync(bf[j], Bs + kk * LDB + wn * 32 + j * 16, LDB);
#pragma unroll
            for (int i = 0; i < 2; i++)
#pragma unroll
                for (int j = 0; j < 2; j++)
                    wmma::mma_sync(acc[i][j], af[i], bf[j], acc[i][j]);
        }
        __syncthreads();
    }

    // epilogue: per-warp smem staging, bias + (silu) + fp16 store
#pragma unroll 1
    for (int mi = 0; mi < 2; mi++) {
        wmma::store_matrix_sync(&Es[warp][0],      acc[mi][0], LDE, wmma::mem_row_major);
        wmma::store_matrix_sync(&Es[warp][0] + 16, acc[mi][1], LDE, wmma::mem_row_major);
        __syncwarp();
        int r  = lane >> 1;
        int cb = (lane & 1) << 4;
        int m  = m0 + wm * 32 + mi * 16 + r;
        if (m < M) {
            int ncol = n0 + wn * 32 + cb;
            __half hv[16];
#pragma unroll
            for (int j = 0; j < 16; j++) {
                float x = Es[warp][r * LDE + cb + j] + bias[ncol + j];
                if (SILU) x = x / (1.0f + expf(-x));
                hv[j] = __float2half_rn(x);
            }
            uint4* dst = (uint4*)(C + (size_t)m * N + ncol);
            dst[0] = ((uint4*)hv)[0];
            dst[1] = ((uint4*)hv)[1];
        }
        __syncwarp();
    }
}

// ---------------------------------------------------------------------------
__device__ __forceinline__ void red_add4(float* p, float4 v) {
    asm volatile("red.global.add.v4.f32 [%0], {%1, %2, %3, %4};"
                 :: "l"(p), "f"(v.x), "f"(v.y), "f"(v.z), "f"(v.w)
                 : "memory");
}

// ---------------------------------------------------------------------------
// Edge kernel: unchanged from round 5 (known 279us).
// ---------------------------------------------------------------------------
__global__ __launch_bounds__(256)
void edge_kernel(const int2*   __restrict__ eidx,
                 const float*  __restrict__ edist,
                 const float*  __restrict__ ediff,
                 const float*  __restrict__ Wf,
                 const float*  __restrict__ bf,
                 const __half* __restrict__ nvec,
                 const __half* __restrict__ so,
                 float* __restrict__ out_s,
                 float* __restrict__ out_v)
{
    __shared__ float s_Wf[NB * F3];
    __shared__ float s_basis[EPB * NB];
    __shared__ float s_cut[EPB];
    __shared__ int   s_src[EPB], s_dst[EPB];
    __shared__ float s_unit[3][EPB];
    __shared__ float s_d[EPB];

    const float PI_C = 0.628318530717958648f;

    int t  = threadIdx.x;
    int e0 = blockIdx.x * EPB;

    for (int i = t; i < NB * F3 / 4; i += 256)
        ((float4*)s_Wf)[i] = ((const float4*)Wf)[i];

    if (t < EPB) {
        int e = e0 + t;
        int2 ei = eidx[e];
        s_dst[t] = ei.x;
        s_src[t] = ei.y;
        float d = edist[e];
        s_d[t] = d;
        s_cut[t] = (d < 5.0f) ? 0.5f * (cosf(d * PI_C) + 1.0f) : 0.0f;
        float inv = 1.0f / d;
        s_unit[0][t] = ediff[e * 3 + 0] * inv;
        s_unit[1][t] = ediff[e * 3 + 1] * inv;
        s_unit[2][t] = ediff[e * 3 + 2] * inv;
    }
    __syncthreads();

    for (int i = t; i < EPB * NB; i += 256) {
        int e = i / NB, n = i % NB;
        float d = s_d[e];
        float x = d * (float)(n + 1) * PI_C;
        x -= 6.2831853071795865f * rintf(x * 0.15915494309189534f);
        s_basis[i] = sinf(x) / d;
    }
    __syncthreads();

    int cg = t & 31;
    int eg = t >> 5;
    int cb = cg << 2;

    float4 bf0 = *(const float4*)&bf[cb];
    float4 bf1 = *(const float4*)&bf[FDIM + cb];
    float4 bf2 = *(const float4*)&bf[2 * FDIM + cb];

#pragma unroll 1
    for (int pass = 0; pass < EPB / 32; pass++) {
        int egg = pass * 8 + eg;

        float acc[4][12];
#pragma unroll
        for (int i = 0; i < 4; i++)
#pragma unroll
            for (int j = 0; j < 12; j++) acc[i][j] = 0.0f;

        const float* bas = &s_basis[(egg << 2) * NB];
#pragma unroll
        for (int k = 0; k < NB; k++) {
            float be[4];
#pragma unroll
            for (int i = 0; i < 4; i++) be[i] = bas[i * NB + k];
            float4 w0 = *(float4*)&s_Wf[k * F3 + cb];
            float4 w1 = *(float4*)&s_Wf[k * F3 + FDIM + cb];
            float4 w2 = *(float4*)&s_Wf[k * F3 + 2 * FDIM + cb];
#pragma unroll
            for (int i = 0; i < 4; i++) {
                acc[i][0] += be[i] * w0.x; acc[i][1] += be[i] * w0.y;
                acc[i][2] += be[i] * w0.z; acc[i][3] += be[i] * w0.w;
                acc[i][4] += be[i] * w1.x; acc[i][5] += be[i] * w1.y;
                acc[i][6] += be[i] * w1.z; acc[i][7] += be[i] * w1.w;
                acc[i][8] += be[i] * w2.x; acc[i][9] += be[i] * w2.y;
                acc[i][10]+= be[i] * w2.z; acc[i][11]+= be[i] * w2.w;
            }
        }

#pragma unroll
        for (int i = 0; i < 4; i++) {
            int e   = (egg << 2) + i;
            int src = s_src[e];
            int dst = s_dst[e];
            float cw = s_cut[e];

            const __half* sor = so + (size_t)src * F3 + cb;
            float4 s0 = ld_half4(sor);
            float4 s1 = ld_half4(sor + FDIM);
            float4 s2 = ld_half4(sor + 2 * FDIM);

            float4 gs, ge, ms;
            gs.x = (acc[i][0] + bf0.x) * cw * s0.x;
            gs.y = (acc[i][1] + bf0.y) * cw * s0.y;
            gs.z = (acc[i][2] + bf0.z) * cw * s0.z;
            gs.w = (acc[i][3] + bf0.w) * cw * s0.w;
            ge.x = (acc[i][4] + bf1.x) * cw * s1.x;
            ge.y = (acc[i][5] + bf1.y) * cw * s1.y;
            ge.z = (acc[i][6] + bf1.z) * cw * s1.z;
            ge.w = (acc[i][7] + bf1.w) * cw * s1.w;
            ms.x = (acc[i][8] + bf2.x) * cw * s2.x;
            ms.y = (acc[i][9] + bf2.y) * cw * s2.y;
            ms.z = (acc[i][10]+ bf2.z) * cw * s2.z;
            ms.w = (acc[i][11]+ bf2.w) * cw * s2.w;

            red_add4(out_s + (size_t)dst * FDIM + cb, ms);

            const __half* nvp = nvec + (size_t)src * F3 + cb;
            float u0 = s_unit[0][e], u1 = s_unit[1][e], u2 = s_unit[2][e];

            float4 v, m;
            v = ld_half4(nvp);
            m.x = v.x * gs.x + ge.x * u0;  m.y = v.y * gs.y + ge.y * u0;
            m.z = v.z * gs.z + ge.z * u0;  m.w = v.w * gs.w + ge.w * u0;
            red_add4(out_v + (size_t)dst * F3 + cb, m);

            v = ld_half4(nvp + FDIM);
            m.x = v.x * gs.x + ge.x * u1;  m.y = v.y * gs.y + ge.y * u1;
            m.z = v.z * gs.z + ge.z * u1;  m.w = v.w * gs.w + ge.w * u1;
            red_add4(out_v + (size_t)dst * F3 + FDIM + cb, m);

            v = ld_half4(nvp + 2 * FDIM);
            m.x = v.x * gs.x + ge.x * u2;  m.y = v.y * gs.y + ge.y * u2;
            m.z = v.z * gs.z + ge.z * u2;  m.w = v.w * gs.w + ge.w * u2;
            red_add4(out_v + (size_t)dst * F3 + 2 * FDIM + cb, m);
        }
    }
}

// ---------------------------------------------------------------------------
extern "C" void kernel_launch(void* const* d_in, const int* in_sizes, int n_in,
                              void* d_out, int out_size) {
    const int2*  eidx  = (const int2*) d_in[0];
    const float* edist = (const float*)d_in[1];
    const float* ediff = (const float*)d_in[2];
    const float* ns    = (const float*)d_in[3];
    const float* nv    = (const float*)d_in[4];
    const float* Wf    = (const float*)d_in[5];
    const float* bf    = (const float*)d_in[6];
    const float* W1    = (const float*)d_in[7];
    const float* b1    = (const float*)d_in[8];
    const float* W2    = (const float*)d_in[9];
    const float* b2    = (const float*)d_in[10];
    float* out = (float*)d_out;

    __half *nsh_ptr, *h_ptr, *so_ptr, *nvh_ptr, *w1h_ptr, *w2h_ptr;
    cudaGetSymbolAddress((void**)&nsh_ptr, g_nsh);
    cudaGetSymbolAddress((void**)&h_ptr,   g_h);
    cudaGetSymbolAddress((void**)&so_ptr,  g_so);
    cudaGetSymbolAddress((void**)&nvh_ptr, g_nvh);
    cudaGetSymbolAddress((void**)&w1h_ptr, g_W1h);
    cudaGetSymbolAddress((void**)&w2h_ptr, g_W2h);

    // 1) concat copy + fp16 conversions of ns/nv
    int tot4 = (NNODES * FDIM + NNODES * F3) / 4;
    copy_init_kernel<<<(tot4 + 255) / 256, 256>>>(
        (const float4*)ns, (const float4*)nv, (float4*)out,
        (uint2*)nsh_ptr, (uint2*)nvh_ptr);

    // 2) weights -> fp16
    f2h_small_kernel<<<(FDIM * FDIM / 4 + 255) / 256, 256>>>(
        (const float4*)W1, (uint2*)w1h_ptr, FDIM * FDIM / 4);
    f2h_small_kernel<<<(FDIM * F3 / 4 + 255) / 256, 256>>>(
        (const float4*)W2, (uint2*)w2h_ptr, FDIM * F3 / 4);

    // 3) h = silu(ns @ W1 + b1)   (tensor cores)
    hgemm_kernel<true><<<dim3((NNODES + 127) / 128, FDIM / 64), 256>>>(
        nsh_ptr, w1h_ptr, b1, h_ptr, NNODES, FDIM);

    // 4) so = h @ W2 + b2         (tensor cores)
    hgemm_kernel<false><<<dim3((NNODES + 127) / 128, F3 / 64), 256>>>(
        h_ptr, w2h_ptr, b2, so_ptr, NNODES, F3);

    // 5) edge messages + scatter-add residuals
    edge_kernel<<<NEDGES / EPB, 256>>>(
        eidx, edist, ediff, Wf, bf, nvh_ptr, so_ptr,
        out, out + (size_t)NNODES * FDIM);
}